// round 1
// baseline (speedup 1.0000x reference)
#include <cuda_runtime.h>

#define NMAX 100000
#define EMAX 1600000
#define GMAX 2048

// persistent scratch (no allocs allowed)
__device__ float g_xw[NMAX * 64];     // x@W result
__device__ float g_h[NMAX * 64];      // aggregation buffer / layer output
__device__ float g_dinv[NMAX];        // degree -> rsqrt(degree)
__device__ float g_norm[EMAX];        // per-edge sym-norm
__device__ int   g_start[GMAX + 1];   // graph row boundaries

__global__ void k_deg_init(int N) {
    int i = blockIdx.x * blockDim.x + threadIdx.x;
    if (i < N) g_dinv[i] = 1.0f;  // self-loop
}

__global__ void k_deg_acc(const int* __restrict__ ei, int E) {
    int e = blockIdx.x * blockDim.x + threadIdx.x;
    if (e < E) atomicAdd(&g_dinv[ei[E + e]], 1.0f);
}

__global__ void k_rsqrt(int N) {
    int i = blockIdx.x * blockDim.x + threadIdx.x;
    if (i < N) g_dinv[i] = rsqrtf(g_dinv[i]);
}

__global__ void k_norm(const int* __restrict__ ei, int E) {
    int e = blockIdx.x * blockDim.x + threadIdx.x;
    if (e < E) g_norm[e] = g_dinv[ei[e]] * g_dinv[ei[E + e]];
}

// xw1 = x[N,6] @ W1[6,64] -> g_xw
__global__ void k_xw1(const float* __restrict__ x, const float* __restrict__ W1, int N) {
    __shared__ float sW[6 * 64];
    for (int t = threadIdx.x; t < 384; t += blockDim.x) sW[t] = W1[t];
    __syncthreads();
    int id = blockIdx.x * blockDim.x + threadIdx.x;
    int row = id >> 6, col = id & 63;
    if (row >= N) return;
    const float* xr = x + row * 6;
    float s = 0.f;
#pragma unroll
    for (int k = 0; k < 6; k++) s += xr[k] * sW[k * 64 + col];
    g_xw[id] = s;
}

// self-loop init: g_h[i,:] = g_xw[i,:] * dinv[i]^2
__global__ void k_agg_init(int N) {
    int id = blockIdx.x * blockDim.x + threadIdx.x;
    if (id >= N * 16) return;
    float di = g_dinv[id >> 4];
    float w = di * di;
    float4 v = ((const float4*)g_xw)[id];
    v.x *= w; v.y *= w; v.z *= w; v.w *= w;
    ((float4*)g_h)[id] = v;
}

// edge scatter: g_h[dst,:] += g_xw[src,:] * norm[e]   (16 threads / edge, vector red)
__global__ void k_scatter(const int* __restrict__ ei, int E) {
    int id = blockIdx.x * blockDim.x + threadIdx.x;
    int e = id >> 4;
    if (e >= E) return;
    int c = id & 15;
    int s = ei[e];
    int d = ei[E + e];
    float wn = g_norm[e];
    float4 v = ((const float4*)g_xw)[s * 16 + c];
    float* p = g_h + d * 64 + c * 4;
    asm volatile("red.global.add.v4.f32 [%0], {%1,%2,%3,%4};"
                 :: "l"(p), "f"(v.x * wn), "f"(v.y * wn), "f"(v.z * wn), "f"(v.w * wn)
                 : "memory");
}

// g_xw = relu(g_h + b1) @ W2   (warp per row; bias+relu of layer1 fused into load)
__global__ void k_xw2(const float* __restrict__ b1, const float* __restrict__ W, int N) {
    __shared__ float sW[64 * 64];
    for (int t = threadIdx.x; t < 4096; t += blockDim.x) sW[t] = W[t];
    __syncthreads();
    int wrp = (blockIdx.x * blockDim.x + threadIdx.x) >> 5;
    int lane = threadIdx.x & 31;
    if (wrp >= N) return;
    float a = fmaxf(g_h[wrp * 64 + lane] + b1[lane], 0.f);
    float b = fmaxf(g_h[wrp * 64 + 32 + lane] + b1[lane + 32], 0.f);
    float s0 = 0.f, s1 = 0.f;
#pragma unroll
    for (int k = 0; k < 32; k++) {
        float v = __shfl_sync(0xffffffffu, a, k);
        s0 += v * sW[k * 64 + lane];
        s1 += v * sW[k * 64 + lane + 32];
    }
#pragma unroll
    for (int k = 0; k < 32; k++) {
        float v = __shfl_sync(0xffffffffu, b, k);
        s0 += v * sW[(k + 32) * 64 + lane];
        s1 += v * sW[(k + 32) * 64 + lane + 32];
    }
    g_xw[wrp * 64 + lane] = s0;
    g_xw[wrp * 64 + lane + 32] = s1;
}

// graph boundaries from sorted batch
__global__ void k_bounds(const int* __restrict__ batch, int N, int G) {
    int i = blockIdx.x * blockDim.x + threadIdx.x;
    if (i >= N) return;
    int b = batch[i];
    if (i == 0) {
        for (int g2 = 0; g2 <= b; g2++) g_start[g2] = 0;
    } else {
        int pb = batch[i - 1];
        for (int g2 = pb + 1; g2 <= b; g2++) g_start[g2] = i;
    }
    if (i == N - 1) {
        for (int g2 = b + 1; g2 <= G; g2++) g_start[g2] = N;
    }
}

// fused: relu(h2+b2) mean-pool + concat embeddings + lin1 + relu + lin2
__global__ void k_final(const float* __restrict__ b2,
                        const int* __restrict__ lig, const int* __restrict__ addv,
                        const int* __restrict__ bas, const int* __restrict__ ary,
                        const float* __restrict__ e_l, const float* __restrict__ e_a,
                        const float* __restrict__ e_b, const float* __restrict__ e_r,
                        const float* __restrict__ l1W, const float* __restrict__ l1b,
                        const float* __restrict__ l2W, const float* __restrict__ l2b,
                        float* __restrict__ out, int G) {
    __shared__ float cat[8][128];
    int lane = threadIdx.x & 31;
    int w = threadIdx.x >> 5;
    int g = blockIdx.x * 8 + w;
    if (g >= G) return;
    int s = g_start[g], e = g_start[g + 1];
    float bias0 = b2[lane], bias1 = b2[lane + 32];
    float a0 = 0.f, a1 = 0.f;
    for (int r = s; r < e; r++) {
        a0 += fmaxf(g_h[r * 64 + lane] + bias0, 0.f);
        a1 += fmaxf(g_h[r * 64 + lane + 32] + bias1, 0.f);
    }
    float inv = 1.0f / fmaxf((float)(e - s), 1.0f);
    cat[w][lane] = a0 * inv;
    cat[w][lane + 32] = a1 * inv;
    if (lane < 16) {
        cat[w][64 + lane]  = e_l[lig[g] * 16 + lane];
        cat[w][80 + lane]  = e_a[addv[g] * 16 + lane];
        cat[w][96 + lane]  = e_b[bas[g] * 16 + lane];
        cat[w][112 + lane] = e_r[ary[g] * 16 + lane];
    }
    __syncwarp();
    float h0 = l1b[lane], h1 = l1b[lane + 32];
#pragma unroll 8
    for (int k = 0; k < 128; k++) {
        float v = cat[w][k];
        h0 += v * l1W[k * 64 + lane];
        h1 += v * l1W[k * 64 + lane + 32];
    }
    h0 = fmaxf(h0, 0.f);
    h1 = fmaxf(h1, 0.f);
    float p = h0 * l2W[lane] + h1 * l2W[lane + 32];
#pragma unroll
    for (int off = 16; off > 0; off >>= 1) p += __shfl_down_sync(0xffffffffu, p, off);
    if (lane == 0) out[g] = p + l2b[0];
}

extern "C" void kernel_launch(void* const* d_in, const int* in_sizes, int n_in,
                              void* d_out, int out_size) {
    const float* x      = (const float*)d_in[0];
    const int*   ei     = (const int*)d_in[1];
    const int*   batch  = (const int*)d_in[2];
    const int*   lig    = (const int*)d_in[3];
    const int*   addv   = (const int*)d_in[4];
    const int*   bas    = (const int*)d_in[5];
    const int*   ary    = (const int*)d_in[6];
    const float* e_l    = (const float*)d_in[7];
    const float* e_a    = (const float*)d_in[8];
    const float* e_b    = (const float*)d_in[9];
    const float* e_r    = (const float*)d_in[10];
    const float* W1     = (const float*)d_in[11];
    const float* b1     = (const float*)d_in[12];
    const float* W2     = (const float*)d_in[13];
    const float* b2     = (const float*)d_in[14];
    const float* l1W    = (const float*)d_in[15];
    const float* l1b    = (const float*)d_in[16];
    const float* l2W    = (const float*)d_in[17];
    const float* l2b    = (const float*)d_in[18];
    float* out = (float*)d_out;

    int N = in_sizes[0] / 6;
    int E = in_sizes[1] / 2;
    int G = out_size;
    const int T = 256;

    k_deg_init<<<(N + T - 1) / T, T>>>(N);
    k_deg_acc<<<(E + T - 1) / T, T>>>(ei, E);
    k_rsqrt<<<(N + T - 1) / T, T>>>(N);
    k_norm<<<(E + T - 1) / T, T>>>(ei, E);

    // layer 1
    k_xw1<<<(N * 64 + T - 1) / T, T>>>(x, W1, N);
    k_agg_init<<<(N * 16 + T - 1) / T, T>>>(N);
    k_scatter<<<(E * 16 + T - 1) / T, T>>>(ei, E);

    // layer 2 (bias+relu of layer1 fused into k_xw2)
    k_xw2<<<(N * 32 + T - 1) / T, T>>>(b1, W2, N);
    k_agg_init<<<(N * 16 + T - 1) / T, T>>>(N);
    k_scatter<<<(E * 16 + T - 1) / T, T>>>(ei, E);

    // readout
    k_bounds<<<(N + T - 1) / T, T>>>(batch, N, G);
    k_final<<<(G + 7) / 8, 256>>>(b2, lig, addv, bas, ary, e_l, e_a, e_b, e_r,
                                  l1W, l1b, l2W, l2b, out, G);
}

// round 2
// speedup vs baseline: 1.2670x; 1.2670x over previous
#include <cuda_runtime.h>

#define NMAX 100000
#define EMAX 1600000
#define GMAX 2048
#define SCAN_BS 512
#define NBLK_MAX ((NMAX + SCAN_BS - 1) / SCAN_BS)

// persistent scratch (no allocs allowed)
__device__ float g_xw[NMAX * 64];     // feature buffer A
__device__ float g_h[NMAX * 64];      // feature buffer B
__device__ float g_dinv[NMAX];        // rsqrt(degree)
__device__ int   g_cnt[NMAX];         // in-degree counts
__device__ int   g_rowptr[NMAX + 1];  // CSR row pointers (by dst)
__device__ int   g_cur[NMAX];         // fill cursors
__device__ int   g_csrc[EMAX];        // CSR src ids
__device__ float g_cw[EMAX];          // CSR edge norms
__device__ int   g_bsum[NBLK_MAX];    // scan block sums
__device__ int   g_boff[NBLK_MAX];    // scan block offsets
__device__ int   g_start[GMAX + 1];   // graph row boundaries

__global__ void k_zero_cnt(int N) {
    int i = blockIdx.x * blockDim.x + threadIdx.x;
    if (i < N) g_cnt[i] = 0;
}

__global__ void k_count(const int* __restrict__ ei, int E) {
    int e = blockIdx.x * blockDim.x + threadIdx.x;
    if (e < E) atomicAdd(&g_cnt[ei[E + e]], 1);
}

// per-block inclusive scan -> exclusive within block + block totals
__global__ void k_scan1(int N) {
    __shared__ int sh[SCAN_BS];
    int i = blockIdx.x * SCAN_BS + threadIdx.x;
    int v = (i < N) ? g_cnt[i] : 0;
    sh[threadIdx.x] = v;
    __syncthreads();
#pragma unroll
    for (int off = 1; off < SCAN_BS; off <<= 1) {
        int t = (threadIdx.x >= off) ? sh[threadIdx.x - off] : 0;
        __syncthreads();
        sh[threadIdx.x] += t;
        __syncthreads();
    }
    if (i < N) g_rowptr[i] = sh[threadIdx.x] - v;  // exclusive within block
    if (threadIdx.x == SCAN_BS - 1) g_bsum[blockIdx.x] = sh[threadIdx.x];
}

// single-block scan of block sums
__global__ void k_scan2(int nb) {
    __shared__ int sh[SCAN_BS];
    int v = (threadIdx.x < nb) ? g_bsum[threadIdx.x] : 0;
    sh[threadIdx.x] = v;
    __syncthreads();
#pragma unroll
    for (int off = 1; off < SCAN_BS; off <<= 1) {
        int t = (threadIdx.x >= off) ? sh[threadIdx.x - off] : 0;
        __syncthreads();
        sh[threadIdx.x] += t;
        __syncthreads();
    }
    if (threadIdx.x < nb) g_boff[threadIdx.x] = sh[threadIdx.x] - v;  // exclusive
}

// add block offsets; init cursors; compute dinv = rsqrt(indeg+1)
__global__ void k_scan3(int N, int E) {
    int i = blockIdx.x * blockDim.x + threadIdx.x;
    if (i >= N) return;
    int rp = g_rowptr[i] + g_boff[i / SCAN_BS];
    g_rowptr[i] = rp;
    g_cur[i] = rp;
    g_dinv[i] = rsqrtf((float)(g_cnt[i] + 1));
    if (i == 0) g_rowptr[N] = E;
}

__global__ void k_fill(const int* __restrict__ ei, int E) {
    int e = blockIdx.x * blockDim.x + threadIdx.x;
    if (e >= E) return;
    int s = ei[e];
    int d = ei[E + e];
    int pos = atomicAdd(&g_cur[d], 1);
    g_csrc[pos] = s;
    g_cw[pos] = g_dinv[s] * g_dinv[d];
}

// xw1 = x[N,6] @ W1[6,64] -> g_xw
__global__ void k_xw1(const float* __restrict__ x, const float* __restrict__ W1, int N) {
    __shared__ float sW[6 * 64];
    for (int t = threadIdx.x; t < 384; t += blockDim.x) sW[t] = W1[t];
    __syncthreads();
    int id = blockIdx.x * blockDim.x + threadIdx.x;
    int row = id >> 6, col = id & 63;
    if (row >= N) return;
    const float* xr = x + row * 6;
    float s = 0.f;
#pragma unroll
    for (int k = 0; k < 6; k++) s += xr[k] * sW[k * 64 + col];
    g_xw[id] = s;
}

// CSR gather: g_h[n,:] = dinv[n]^2 * g_xw[n,:] + sum_e w_e * g_xw[src_e,:]
// 16 threads per node (one float4 lane each)
__global__ void k_gather(int N) {
    int id = blockIdx.x * blockDim.x + threadIdx.x;
    int n = id >> 4;
    if (n >= N) return;
    int c = id & 15;
    const float4* xw4 = (const float4*)g_xw;
    float di = g_dinv[n];
    float w0 = di * di;
    float4 v = xw4[n * 16 + c];
    float ax = v.x * w0, ay = v.y * w0, az = v.z * w0, aw = v.w * w0;
    int k = g_rowptr[n], end = g_rowptr[n + 1];
    for (; k + 1 < end; k += 2) {
        int s0 = g_csrc[k], s1 = g_csrc[k + 1];
        float e0 = g_cw[k], e1 = g_cw[k + 1];
        float4 a = xw4[s0 * 16 + c];
        float4 b = xw4[s1 * 16 + c];
        ax += a.x * e0 + b.x * e1;
        ay += a.y * e0 + b.y * e1;
        az += a.z * e0 + b.z * e1;
        aw += a.w * e0 + b.w * e1;
    }
    if (k < end) {
        int s0 = g_csrc[k];
        float e0 = g_cw[k];
        float4 a = xw4[s0 * 16 + c];
        ax += a.x * e0; ay += a.y * e0; az += a.z * e0; aw += a.w * e0;
    }
    ((float4*)g_h)[n * 16 + c] = make_float4(ax, ay, az, aw);
}

// g_xw = relu(g_h + b1) @ W2   (warp per row)
__global__ void k_xw2(const float* __restrict__ b1, const float* __restrict__ W, int N) {
    __shared__ float sW[64 * 64];
    for (int t = threadIdx.x; t < 4096; t += blockDim.x) sW[t] = W[t];
    __syncthreads();
    int wrp = (blockIdx.x * blockDim.x + threadIdx.x) >> 5;
    int lane = threadIdx.x & 31;
    if (wrp >= N) return;
    float a = fmaxf(g_h[wrp * 64 + lane] + b1[lane], 0.f);
    float b = fmaxf(g_h[wrp * 64 + 32 + lane] + b1[lane + 32], 0.f);
    float s0 = 0.f, s1 = 0.f;
#pragma unroll
    for (int k = 0; k < 32; k++) {
        float v = __shfl_sync(0xffffffffu, a, k);
        s0 += v * sW[k * 64 + lane];
        s1 += v * sW[k * 64 + lane + 32];
    }
#pragma unroll
    for (int k = 0; k < 32; k++) {
        float v = __shfl_sync(0xffffffffu, b, k);
        s0 += v * sW[(k + 32) * 64 + lane];
        s1 += v * sW[(k + 32) * 64 + lane + 32];
    }
    g_xw[wrp * 64 + lane] = s0;
    g_xw[wrp * 64 + lane + 32] = s1;
}

// graph boundaries from sorted batch
__global__ void k_bounds(const int* __restrict__ batch, int N, int G) {
    int i = blockIdx.x * blockDim.x + threadIdx.x;
    if (i >= N) return;
    int b = batch[i];
    if (i == 0) {
        for (int g2 = 0; g2 <= b; g2++) g_start[g2] = 0;
    } else {
        int pb = batch[i - 1];
        for (int g2 = pb + 1; g2 <= b; g2++) g_start[g2] = i;
    }
    if (i == N - 1) {
        for (int g2 = b + 1; g2 <= G; g2++) g_start[g2] = N;
    }
}

// fused: relu(h2+b2) mean-pool + concat embeddings + lin1 + relu + lin2
__global__ void k_final(const float* __restrict__ b2,
                        const int* __restrict__ lig, const int* __restrict__ addv,
                        const int* __restrict__ bas, const int* __restrict__ ary,
                        const float* __restrict__ e_l, const float* __restrict__ e_a,
                        const float* __restrict__ e_b, const float* __restrict__ e_r,
                        const float* __restrict__ l1W, const float* __restrict__ l1b,
                        const float* __restrict__ l2W, const float* __restrict__ l2b,
                        float* __restrict__ out, int G) {
    __shared__ float cat[8][128];
    int lane = threadIdx.x & 31;
    int w = threadIdx.x >> 5;
    int g = blockIdx.x * 8 + w;
    if (g >= G) return;
    int s = g_start[g], e = g_start[g + 1];
    float bias0 = b2[lane], bias1 = b2[lane + 32];
    float a0 = 0.f, a1 = 0.f;
    for (int r = s; r < e; r++) {
        a0 += fmaxf(g_h[r * 64 + lane] + bias0, 0.f);
        a1 += fmaxf(g_h[r * 64 + 32 + lane] + bias1, 0.f);
    }
    float inv = 1.0f / fmaxf((float)(e - s), 1.0f);
    cat[w][lane] = a0 * inv;
    cat[w][lane + 32] = a1 * inv;
    if (lane < 16) {
        cat[w][64 + lane]  = e_l[lig[g] * 16 + lane];
        cat[w][80 + lane]  = e_a[addv[g] * 16 + lane];
        cat[w][96 + lane]  = e_b[bas[g] * 16 + lane];
        cat[w][112 + lane] = e_r[ary[g] * 16 + lane];
    }
    __syncwarp();
    float h0 = l1b[lane], h1 = l1b[lane + 32];
#pragma unroll 8
    for (int k = 0; k < 128; k++) {
        float v = cat[w][k];
        h0 += v * l1W[k * 64 + lane];
        h1 += v * l1W[k * 64 + lane + 32];
    }
    h0 = fmaxf(h0, 0.f);
    h1 = fmaxf(h1, 0.f);
    float p = h0 * l2W[lane] + h1 * l2W[lane + 32];
#pragma unroll
    for (int off = 16; off > 0; off >>= 1) p += __shfl_down_sync(0xffffffffu, p, off);
    if (lane == 0) out[g] = p + l2b[0];
}

extern "C" void kernel_launch(void* const* d_in, const int* in_sizes, int n_in,
                              void* d_out, int out_size) {
    const float* x      = (const float*)d_in[0];
    const int*   ei     = (const int*)d_in[1];
    const int*   batch  = (const int*)d_in[2];
    const int*   lig    = (const int*)d_in[3];
    const int*   addv   = (const int*)d_in[4];
    const int*   bas    = (const int*)d_in[5];
    const int*   ary    = (const int*)d_in[6];
    const float* e_l    = (const float*)d_in[7];
    const float* e_a    = (const float*)d_in[8];
    const float* e_b    = (const float*)d_in[9];
    const float* e_r    = (const float*)d_in[10];
    const float* W1     = (const float*)d_in[11];
    const float* b1     = (const float*)d_in[12];
    const float* W2     = (const float*)d_in[13];
    const float* b2     = (const float*)d_in[14];
    const float* l1W    = (const float*)d_in[15];
    const float* l1b    = (const float*)d_in[16];
    const float* l2W    = (const float*)d_in[17];
    const float* l2b    = (const float*)d_in[18];
    float* out = (float*)d_out;

    int N = in_sizes[0] / 6;
    int E = in_sizes[1] / 2;
    int G = out_size;
    const int T = 256;
    int nb = (N + SCAN_BS - 1) / SCAN_BS;

    // build dst-CSR + dinv
    k_zero_cnt<<<(N + T - 1) / T, T>>>(N);
    k_count<<<(E + T - 1) / T, T>>>(ei, E);
    k_scan1<<<nb, SCAN_BS>>>(N);
    k_scan2<<<1, SCAN_BS>>>(nb);
    k_scan3<<<(N + T - 1) / T, T>>>(N, E);
    k_fill<<<(E + T - 1) / T, T>>>(ei, E);

    // layer 1
    k_xw1<<<(N * 64 + T - 1) / T, T>>>(x, W1, N);
    k_gather<<<(N * 16 + T - 1) / T, T>>>(N);

    // layer 2
    k_xw2<<<(N * 32 + T - 1) / T, T>>>(b1, W2, N);
    k_gather<<<(N * 16 + T - 1) / T, T>>>(N);

    // readout
    k_bounds<<<(N + T - 1) / T, T>>>(batch, N, G);
    k_final<<<(G + 7) / 8, 256>>>(b2, lig, addv, bas, ary, e_l, e_a, e_b, e_r,
                                  l1W, l1b, l2W, l2b, out, G);
}

// round 3
// speedup vs baseline: 1.4491x; 1.1438x over previous
#include <cuda_runtime.h>

#define NMAX 100000
#define EMAX 1600000
#define GMAX 2048
#define SCAN_BS 512
#define NBLK_MAX ((NMAX + SCAN_BS - 1) / SCAN_BS)

// persistent scratch (no allocs allowed)
__device__ float g_xw[NMAX * 64];     // feature buffer A
__device__ float g_h[NMAX * 64];      // feature buffer B
__device__ float g_dinv[NMAX];        // rsqrt(degree)
__device__ int   g_cnt[NMAX];         // in-degree counts
__device__ int   g_rowptr[NMAX + 1];  // CSR row pointers (by dst)
__device__ int   g_cur[NMAX];         // fill cursors
__device__ int   g_csrc[EMAX];        // CSR src ids
__device__ float g_cw[EMAX];          // CSR edge norms
__device__ int   g_bsum[NBLK_MAX];    // scan block sums
__device__ int   g_start[GMAX + 1];   // graph row boundaries

__global__ void k_zero_cnt(int N) {
    int i = blockIdx.x * blockDim.x + threadIdx.x;
    if (i < N) g_cnt[i] = 0;
}

__global__ void k_count(const int* __restrict__ ei, int E) {
    int e = blockIdx.x * blockDim.x + threadIdx.x;
    if (e < E) atomicAdd(&g_cnt[ei[E + e]], 1);
}

// per-block inclusive scan -> exclusive within block + block totals
__global__ void k_scan1(int N) {
    __shared__ int sh[SCAN_BS];
    int i = blockIdx.x * SCAN_BS + threadIdx.x;
    int v = (i < N) ? g_cnt[i] : 0;
    sh[threadIdx.x] = v;
    __syncthreads();
#pragma unroll
    for (int off = 1; off < SCAN_BS; off <<= 1) {
        int t = (threadIdx.x >= off) ? sh[threadIdx.x - off] : 0;
        __syncthreads();
        sh[threadIdx.x] += t;
        __syncthreads();
    }
    if (i < N) g_rowptr[i] = sh[threadIdx.x] - v;  // exclusive within block
    if (threadIdx.x == SCAN_BS - 1) g_bsum[blockIdx.x] = sh[threadIdx.x];
}

// fused: block offset (redundant reduce of block sums) + rowptr finalize +
// cursor init + dinv
__global__ void k_scan3(int N, int E) {
    __shared__ int warp_part[SCAN_BS / 32];
    __shared__ int s_off;
    int part = 0;
    for (int j = threadIdx.x; j < blockIdx.x; j += SCAN_BS) part += g_bsum[j];
#pragma unroll
    for (int o = 16; o; o >>= 1) part += __shfl_down_sync(0xffffffffu, part, o);
    if ((threadIdx.x & 31) == 0) warp_part[threadIdx.x >> 5] = part;
    __syncthreads();
    if (threadIdx.x == 0) {
        int t = 0;
#pragma unroll
        for (int w = 0; w < SCAN_BS / 32; w++) t += warp_part[w];
        s_off = t;
    }
    __syncthreads();
    int i = blockIdx.x * SCAN_BS + threadIdx.x;
    if (i < N) {
        int rp = g_rowptr[i] + s_off;
        g_rowptr[i] = rp;
        g_cur[i] = rp;
        g_dinv[i] = rsqrtf((float)(g_cnt[i] + 1));
        if (i == 0) g_rowptr[N] = E;
    }
}

__global__ void k_fill(const int* __restrict__ ei, int E) {
    int e = blockIdx.x * blockDim.x + threadIdx.x;
    if (e >= E) return;
    int s = ei[e];
    int d = ei[E + e];
    int pos = atomicAdd(&g_cur[d], 1);
    g_csrc[pos] = s;
    g_cw[pos] = g_dinv[s] * g_dinv[d];
}

// xw1 = x[N,6] @ W1[6,64] -> g_xw
__global__ void k_xw1(const float* __restrict__ x, const float* __restrict__ W1, int N) {
    __shared__ float sW[6 * 64];
    for (int t = threadIdx.x; t < 384; t += blockDim.x) sW[t] = W1[t];
    __syncthreads();
    int id = blockIdx.x * blockDim.x + threadIdx.x;
    int row = id >> 6, col = id & 63;
    if (row >= N) return;
    const float* xr = x + row * 6;
    float s = 0.f;
#pragma unroll
    for (int k = 0; k < 6; k++) s += xr[k] * sW[k * 64 + col];
    g_xw[id] = s;
}

// CSR gather: g_h[n,:] = dinv[n]^2 * g_xw[n,:] + sum_e w_e * g_xw[src_e,:]
// 16 threads per node; 4-way unrolled with independent accumulators for MLP
__global__ void k_gather(int N) {
    int id = blockIdx.x * blockDim.x + threadIdx.x;
    int n = id >> 4;
    if (n >= N) return;
    int c = id & 15;
    const float4* __restrict__ xw4 = (const float4*)g_xw;
    float di = g_dinv[n];
    float w0 = di * di;
    float4 v = xw4[n * 16 + c];
    float4 A0 = make_float4(v.x * w0, v.y * w0, v.z * w0, v.w * w0);
    float4 A1 = make_float4(0.f, 0.f, 0.f, 0.f);
    float4 A2 = make_float4(0.f, 0.f, 0.f, 0.f);
    float4 A3 = make_float4(0.f, 0.f, 0.f, 0.f);
    int k = g_rowptr[n], end = g_rowptr[n + 1];
    for (; k + 3 < end; k += 4) {
        int s0 = g_csrc[k], s1 = g_csrc[k + 1], s2 = g_csrc[k + 2], s3 = g_csrc[k + 3];
        float e0 = g_cw[k], e1 = g_cw[k + 1], e2 = g_cw[k + 2], e3 = g_cw[k + 3];
        float4 a = xw4[s0 * 16 + c];
        float4 b = xw4[s1 * 16 + c];
        float4 cc = xw4[s2 * 16 + c];
        float4 d = xw4[s3 * 16 + c];
        A0.x += a.x * e0;  A0.y += a.y * e0;  A0.z += a.z * e0;  A0.w += a.w * e0;
        A1.x += b.x * e1;  A1.y += b.y * e1;  A1.z += b.z * e1;  A1.w += b.w * e1;
        A2.x += cc.x * e2; A2.y += cc.y * e2; A2.z += cc.z * e2; A2.w += cc.w * e2;
        A3.x += d.x * e3;  A3.y += d.y * e3;  A3.z += d.z * e3;  A3.w += d.w * e3;
    }
    for (; k < end; k++) {
        int s0 = g_csrc[k];
        float e0 = g_cw[k];
        float4 a = xw4[s0 * 16 + c];
        A0.x += a.x * e0; A0.y += a.y * e0; A0.z += a.z * e0; A0.w += a.w * e0;
    }
    A0.x += A1.x + A2.x + A3.x;
    A0.y += A1.y + A2.y + A3.y;
    A0.z += A1.z + A2.z + A3.z;
    A0.w += A1.w + A2.w + A3.w;
    ((float4*)g_h)[n * 16 + c] = A0;
}

// g_xw = relu(g_h + b1) @ W2   (4 rows per warp, register-blocked)
__global__ void k_xw2(const float* __restrict__ b1, const float* __restrict__ W, int N) {
    __shared__ float sW[64 * 64];
    for (int t = threadIdx.x; t < 4096; t += blockDim.x) sW[t] = W[t];
    __syncthreads();
    int wrp = (blockIdx.x * blockDim.x + threadIdx.x) >> 5;
    int lane = threadIdx.x & 31;
    int r0 = wrp * 4;
    if (r0 >= N) return;
    float bl = b1[lane], bh = b1[lane + 32];
    float alo[4], ahi[4];
#pragma unroll
    for (int r = 0; r < 4; r++) {
        int row = r0 + r;
        if (row < N) {
            alo[r] = fmaxf(g_h[row * 64 + lane] + bl, 0.f);
            ahi[r] = fmaxf(g_h[row * 64 + 32 + lane] + bh, 0.f);
        } else { alo[r] = 0.f; ahi[r] = 0.f; }
    }
    float s0[4] = {0.f, 0.f, 0.f, 0.f};
    float s1[4] = {0.f, 0.f, 0.f, 0.f};
#pragma unroll
    for (int k = 0; k < 32; k++) {
        float w0 = sW[k * 64 + lane];
        float w1 = sW[k * 64 + lane + 32];
#pragma unroll
        for (int r = 0; r < 4; r++) {
            float vv = __shfl_sync(0xffffffffu, alo[r], k);
            s0[r] += vv * w0;
            s1[r] += vv * w1;
        }
    }
#pragma unroll
    for (int k = 0; k < 32; k++) {
        float w0 = sW[(k + 32) * 64 + lane];
        float w1 = sW[(k + 32) * 64 + lane + 32];
#pragma unroll
        for (int r = 0; r < 4; r++) {
            float vv = __shfl_sync(0xffffffffu, ahi[r], k);
            s0[r] += vv * w0;
            s1[r] += vv * w1;
        }
    }
#pragma unroll
    for (int r = 0; r < 4; r++) {
        int row = r0 + r;
        if (row < N) {
            g_xw[row * 64 + lane] = s0[r];
            g_xw[row * 64 + lane + 32] = s1[r];
        }
    }
}

// graph boundaries from sorted batch
__global__ void k_bounds(const int* __restrict__ batch, int N, int G) {
    int i = blockIdx.x * blockDim.x + threadIdx.x;
    if (i >= N) return;
    int b = batch[i];
    if (i == 0) {
        for (int g2 = 0; g2 <= b; g2++) g_start[g2] = 0;
    } else {
        int pb = batch[i - 1];
        for (int g2 = pb + 1; g2 <= b; g2++) g_start[g2] = i;
    }
    if (i == N - 1) {
        for (int g2 = b + 1; g2 <= G; g2++) g_start[g2] = N;
    }
}

// fused: relu(h2+b2) mean-pool + concat embeddings + lin1 + relu + lin2
__global__ void k_final(const float* __restrict__ b2,
                        const int* __restrict__ lig, const int* __restrict__ addv,
                        const int* __restrict__ bas, const int* __restrict__ ary,
                        const float* __restrict__ e_l, const float* __restrict__ e_a,
                        const float* __restrict__ e_b, const float* __restrict__ e_r,
                        const float* __restrict__ l1W, const float* __restrict__ l1b,
                        const float* __restrict__ l2W, const float* __restrict__ l2b,
                        float* __restrict__ out, int G) {
    __shared__ float cat[8][128];
    int lane = threadIdx.x & 31;
    int w = threadIdx.x >> 5;
    int g = blockIdx.x * 8 + w;
    if (g >= G) return;
    int s = g_start[g], e = g_start[g + 1];
    float bias0 = b2[lane], bias1 = b2[lane + 32];
    float a0 = 0.f, a1 = 0.f;
    for (int r = s; r < e; r++) {
        a0 += fmaxf(g_h[r * 64 + lane] + bias0, 0.f);
        a1 += fmaxf(g_h[r * 64 + 32 + lane] + bias1, 0.f);
    }
    float inv = 1.0f / fmaxf((float)(e - s), 1.0f);
    cat[w][lane] = a0 * inv;
    cat[w][lane + 32] = a1 * inv;
    if (lane < 16) {
        cat[w][64 + lane]  = e_l[lig[g] * 16 + lane];
        cat[w][80 + lane]  = e_a[addv[g] * 16 + lane];
        cat[w][96 + lane]  = e_b[bas[g] * 16 + lane];
        cat[w][112 + lane] = e_r[ary[g] * 16 + lane];
    }
    __syncwarp();
    float h0 = l1b[lane], h1 = l1b[lane + 32];
#pragma unroll 8
    for (int k = 0; k < 128; k++) {
        float v = cat[w][k];
        h0 += v * l1W[k * 64 + lane];
        h1 += v * l1W[k * 64 + lane + 32];
    }
    h0 = fmaxf(h0, 0.f);
    h1 = fmaxf(h1, 0.f);
    float p = h0 * l2W[lane] + h1 * l2W[lane + 32];
#pragma unroll
    for (int off = 16; off > 0; off >>= 1) p += __shfl_down_sync(0xffffffffu, p, off);
    if (lane == 0) out[g] = p + l2b[0];
}

extern "C" void kernel_launch(void* const* d_in, const int* in_sizes, int n_in,
                              void* d_out, int out_size) {
    const float* x      = (const float*)d_in[0];
    const int*   ei     = (const int*)d_in[1];
    const int*   batch  = (const int*)d_in[2];
    const int*   lig    = (const int*)d_in[3];
    const int*   addv   = (const int*)d_in[4];
    const int*   bas    = (const int*)d_in[5];
    const int*   ary    = (const int*)d_in[6];
    const float* e_l    = (const float*)d_in[7];
    const float* e_a    = (const float*)d_in[8];
    const float* e_b    = (const float*)d_in[9];
    const float* e_r    = (const float*)d_in[10];
    const float* W1     = (const float*)d_in[11];
    const float* b1     = (const float*)d_in[12];
    const float* W2     = (const float*)d_in[13];
    const float* b2     = (const float*)d_in[14];
    const float* l1W    = (const float*)d_in[15];
    const float* l1b    = (const float*)d_in[16];
    const float* l2W    = (const float*)d_in[17];
    const float* l2b    = (const float*)d_in[18];
    float* out = (float*)d_out;

    int N = in_sizes[0] / 6;
    int E = in_sizes[1] / 2;
    int G = out_size;
    const int T = 256;
    int nb = (N + SCAN_BS - 1) / SCAN_BS;

    // build dst-CSR + dinv
    k_zero_cnt<<<(N + T - 1) / T, T>>>(N);
    k_count<<<(E + T - 1) / T, T>>>(ei, E);
    k_scan1<<<nb, SCAN_BS>>>(N);
    k_scan3<<<nb, SCAN_BS>>>(N, E);
    k_fill<<<(E + T - 1) / T, T>>>(ei, E);

    // layer 1
    k_xw1<<<(N * 64 + T - 1) / T, T>>>(x, W1, N);
    k_gather<<<(N * 16 + T - 1) / T, T>>>(N);

    // layer 2
    k_xw2<<<((N + 3) / 4 * 32 + T - 1) / T, T>>>(b1, W2, N);
    k_gather<<<(N * 16 + T - 1) / T, T>>>(N);

    // readout
    k_bounds<<<(N + T - 1) / T, T>>>(batch, N, G);
    k_final<<<(G + 7) / 8, 256>>>(b2, lig, addv, bas, ary, e_l, e_a, e_b, e_r,
                                  l1W, l1b, l2W, l2b, out, G);
}

// round 4
// speedup vs baseline: 1.8250x; 1.2594x over previous
#include <cuda_runtime.h>
#include <cuda_fp16.h>

#define NMAX 100000
#define EMAX 1600000
#define GMAX 2048
#define SCAN_BS 512
#define NBLK_MAX ((NMAX + SCAN_BS - 1) / SCAN_BS)

// persistent scratch (no allocs allowed)
__device__ __align__(16) __half g_xwh[NMAX * 64];  // fp16 feature buffer (matmul outputs)
__device__ float g_h[NMAX * 64];      // fp32 aggregation output
__device__ float g_dinv[NMAX];        // rsqrt(degree)
__device__ int   g_cnt[NMAX];         // in-degree counts
__device__ int   g_rowptr[NMAX + 1];  // CSR row pointers (by dst)
__device__ int   g_cur[NMAX];         // fill cursors
__device__ __align__(8) int2 g_csrcw[EMAX];  // CSR packed {src, weight-bits}
__device__ int   g_bsum[NBLK_MAX];    // scan block sums
__device__ int   g_start[GMAX + 1];   // graph row boundaries

__global__ void k_zero_cnt(int N) {
    int i = blockIdx.x * blockDim.x + threadIdx.x;
    if (i < N) g_cnt[i] = 0;
}

// fused: degree count (id < E) + xw1 = x@W1 -> half (id < N*64)
__global__ void k_count_xw1(const int* __restrict__ ei,
                            const float* __restrict__ x,
                            const float* __restrict__ W1, int E, int N) {
    __shared__ float sW[6 * 64];
    for (int t = threadIdx.x; t < 384; t += blockDim.x) sW[t] = W1[t];
    __syncthreads();
    int id = blockIdx.x * blockDim.x + threadIdx.x;
    if (id < E) atomicAdd(&g_cnt[ei[E + id]], 1);
    int row = id >> 6, col = id & 63;
    if (row < N) {
        const float* xr = x + row * 6;
        float s = 0.f;
#pragma unroll
        for (int k = 0; k < 6; k++) s += xr[k] * sW[k * 64 + col];
        g_xwh[id] = __float2half_rn(s);
    }
}

// per-block inclusive scan -> exclusive within block + block totals
__global__ void k_scan1(int N) {
    __shared__ int sh[SCAN_BS];
    int i = blockIdx.x * SCAN_BS + threadIdx.x;
    int v = (i < N) ? g_cnt[i] : 0;
    sh[threadIdx.x] = v;
    __syncthreads();
#pragma unroll
    for (int off = 1; off < SCAN_BS; off <<= 1) {
        int t = (threadIdx.x >= off) ? sh[threadIdx.x - off] : 0;
        __syncthreads();
        sh[threadIdx.x] += t;
        __syncthreads();
    }
    if (i < N) g_rowptr[i] = sh[threadIdx.x] - v;
    if (threadIdx.x == SCAN_BS - 1) g_bsum[blockIdx.x] = sh[threadIdx.x];
}

// block offset (redundant reduce) + rowptr finalize + cursor init + dinv
__global__ void k_scan3(int N, int E) {
    __shared__ int warp_part[SCAN_BS / 32];
    __shared__ int s_off;
    int part = 0;
    for (int j = threadIdx.x; j < blockIdx.x; j += SCAN_BS) part += g_bsum[j];
#pragma unroll
    for (int o = 16; o; o >>= 1) part += __shfl_down_sync(0xffffffffu, part, o);
    if ((threadIdx.x & 31) == 0) warp_part[threadIdx.x >> 5] = part;
    __syncthreads();
    if (threadIdx.x == 0) {
        int t = 0;
#pragma unroll
        for (int w = 0; w < SCAN_BS / 32; w++) t += warp_part[w];
        s_off = t;
    }
    __syncthreads();
    int i = blockIdx.x * SCAN_BS + threadIdx.x;
    if (i < N) {
        int rp = g_rowptr[i] + s_off;
        g_rowptr[i] = rp;
        g_cur[i] = rp;
        g_dinv[i] = rsqrtf((float)(g_cnt[i] + 1));
        if (i == 0) g_rowptr[N] = E;
    }
}

// fused: CSR fill (id < E) + graph bounds from sorted batch (id < N)
__global__ void k_fill_bounds(const int* __restrict__ ei,
                              const int* __restrict__ batch,
                              int E, int N, int G) {
    int id = blockIdx.x * blockDim.x + threadIdx.x;
    if (id < E) {
        int s = ei[id];
        int d = ei[E + id];
        int pos = atomicAdd(&g_cur[d], 1);
        float w = g_dinv[s] * g_dinv[d];
        g_csrcw[pos] = make_int2(s, __float_as_int(w));
    }
    if (id < N) {
        int b = batch[id];
        if (id == 0) {
            for (int g2 = 0; g2 <= b; g2++) g_start[g2] = 0;
        } else {
            int pb = batch[id - 1];
            for (int g2 = pb + 1; g2 <= b; g2++) g_start[g2] = id;
        }
        if (id == N - 1) {
            for (int g2 = b + 1; g2 <= G; g2++) g_start[g2] = N;
        }
    }
}

__device__ __forceinline__ void h8_fma(float* acc, uint4 r, float w) {
    __half2* h = (__half2*)&r;
#pragma unroll
    for (int i = 0; i < 4; i++) {
        float2 f = __half22float2(h[i]);
        acc[2 * i]     += f.x * w;
        acc[2 * i + 1] += f.y * w;
    }
}

// CSR gather: g_h[n,:] = dinv^2 * xw[n,:] + sum_e w_e * xw[src_e,:]
// 8 threads/node, each owns 8 half features (one uint4 load per edge)
__global__ void k_gather(int N) {
    int id = blockIdx.x * blockDim.x + threadIdx.x;
    int n = id >> 3;
    if (n >= N) return;
    int c = id & 7;
    const uint4* __restrict__ xw4 = (const uint4*)g_xwh;  // row = 8 uint4
    float di = g_dinv[n];
    float w0 = di * di;
    float A[8] = {0, 0, 0, 0, 0, 0, 0, 0};
    float B[8] = {0, 0, 0, 0, 0, 0, 0, 0};
    h8_fma(A, xw4[n * 8 + c], w0);
    int k = g_rowptr[n], end = g_rowptr[n + 1];
    for (; k + 1 < end; k += 2) {
        int2 e0 = g_csrcw[k];
        int2 e1 = g_csrcw[k + 1];
        uint4 r0 = xw4[e0.x * 8 + c];
        uint4 r1 = xw4[e1.x * 8 + c];
        h8_fma(A, r0, __int_as_float(e0.y));
        h8_fma(B, r1, __int_as_float(e1.y));
    }
    if (k < end) {
        int2 e0 = g_csrcw[k];
        h8_fma(A, xw4[e0.x * 8 + c], __int_as_float(e0.y));
    }
    float4* out4 = (float4*)(g_h + n * 64 + c * 8);
    out4[0] = make_float4(A[0] + B[0], A[1] + B[1], A[2] + B[2], A[3] + B[3]);
    out4[1] = make_float4(A[4] + B[4], A[5] + B[5], A[6] + B[6], A[7] + B[7]);
}

// g_xwh = half(relu(g_h + b1) @ W2)   (4 rows per warp, register-blocked)
__global__ void k_xw2(const float* __restrict__ b1, const float* __restrict__ W, int N) {
    __shared__ float sW[64 * 64];
    for (int t = threadIdx.x; t < 4096; t += blockDim.x) sW[t] = W[t];
    __syncthreads();
    int wrp = (blockIdx.x * blockDim.x + threadIdx.x) >> 5;
    int lane = threadIdx.x & 31;
    int r0 = wrp * 4;
    if (r0 >= N) return;
    float bl = b1[lane], bh = b1[lane + 32];
    float alo[4], ahi[4];
#pragma unroll
    for (int r = 0; r < 4; r++) {
        int row = r0 + r;
        if (row < N) {
            alo[r] = fmaxf(g_h[row * 64 + lane] + bl, 0.f);
            ahi[r] = fmaxf(g_h[row * 64 + 32 + lane] + bh, 0.f);
        } else { alo[r] = 0.f; ahi[r] = 0.f; }
    }
    float s0[4] = {0.f, 0.f, 0.f, 0.f};
    float s1[4] = {0.f, 0.f, 0.f, 0.f};
#pragma unroll
    for (int k = 0; k < 32; k++) {
        float w0 = sW[k * 64 + lane];
        float w1 = sW[k * 64 + lane + 32];
#pragma unroll
        for (int r = 0; r < 4; r++) {
            float vv = __shfl_sync(0xffffffffu, alo[r], k);
            s0[r] += vv * w0;
            s1[r] += vv * w1;
        }
    }
#pragma unroll
    for (int k = 0; k < 32; k++) {
        float w0 = sW[(k + 32) * 64 + lane];
        float w1 = sW[(k + 32) * 64 + lane + 32];
#pragma unroll
        for (int r = 0; r < 4; r++) {
            float vv = __shfl_sync(0xffffffffu, ahi[r], k);
            s0[r] += vv * w0;
            s1[r] += vv * w1;
        }
    }
#pragma unroll
    for (int r = 0; r < 4; r++) {
        int row = r0 + r;
        if (row < N) {
            g_xwh[row * 64 + lane]      = __float2half_rn(s0[r]);
            g_xwh[row * 64 + lane + 32] = __float2half_rn(s1[r]);
        }
    }
}

// fused: relu(h2+b2) mean-pool + concat embeddings + lin1 + relu + lin2
__global__ void k_final(const float* __restrict__ b2,
                        const int* __restrict__ lig, const int* __restrict__ addv,
                        const int* __restrict__ bas, const int* __restrict__ ary,
                        const float* __restrict__ e_l, const float* __restrict__ e_a,
                        const float* __restrict__ e_b, const float* __restrict__ e_r,
                        const float* __restrict__ l1W, const float* __restrict__ l1b,
                        const float* __restrict__ l2W, const float* __restrict__ l2b,
                        float* __restrict__ out, int G) {
    __shared__ float cat[8][128];
    int lane = threadIdx.x & 31;
    int w = threadIdx.x >> 5;
    int g = blockIdx.x * 8 + w;
    if (g >= G) return;
    int s = g_start[g], e = g_start[g + 1];
    float bias0 = b2[lane], bias1 = b2[lane + 32];
    float a0 = 0.f, a1 = 0.f;
    for (int r = s; r < e; r++) {
        a0 += fmaxf(g_h[r * 64 + lane] + bias0, 0.f);
        a1 += fmaxf(g_h[r * 64 + 32 + lane] + bias1, 0.f);
    }
    float inv = 1.0f / fmaxf((float)(e - s), 1.0f);
    cat[w][lane] = a0 * inv;
    cat[w][lane + 32] = a1 * inv;
    if (lane < 16) {
        cat[w][64 + lane]  = e_l[lig[g] * 16 + lane];
        cat[w][80 + lane]  = e_a[addv[g] * 16 + lane];
        cat[w][96 + lane]  = e_b[bas[g] * 16 + lane];
        cat[w][112 + lane] = e_r[ary[g] * 16 + lane];
    }
    __syncwarp();
    float h0 = l1b[lane], h1 = l1b[lane + 32];
#pragma unroll 8
    for (int k = 0; k < 128; k++) {
        float v = cat[w][k];
        h0 += v * l1W[k * 64 + lane];
        h1 += v * l1W[k * 64 + lane + 32];
    }
    h0 = fmaxf(h0, 0.f);
    h1 = fmaxf(h1, 0.f);
    float p = h0 * l2W[lane] + h1 * l2W[lane + 32];
#pragma unroll
    for (int off = 16; off > 0; off >>= 1) p += __shfl_down_sync(0xffffffffu, p, off);
    if (lane == 0) out[g] = p + l2b[0];
}

extern "C" void kernel_launch(void* const* d_in, const int* in_sizes, int n_in,
                              void* d_out, int out_size) {
    const float* x      = (const float*)d_in[0];
    const int*   ei     = (const int*)d_in[1];
    const int*   batch  = (const int*)d_in[2];
    const int*   lig    = (const int*)d_in[3];
    const int*   addv   = (const int*)d_in[4];
    const int*   bas    = (const int*)d_in[5];
    const int*   ary    = (const int*)d_in[6];
    const float* e_l    = (const float*)d_in[7];
    const float* e_a    = (const float*)d_in[8];
    const float* e_b    = (const float*)d_in[9];
    const float* e_r    = (const float*)d_in[10];
    const float* W1     = (const float*)d_in[11];
    const float* b1     = (const float*)d_in[12];
    const float* W2     = (const float*)d_in[13];
    const float* b2     = (const float*)d_in[14];
    const float* l1W    = (const float*)d_in[15];
    const float* l1b    = (const float*)d_in[16];
    const float* l2W    = (const float*)d_in[17];
    const float* l2b    = (const float*)d_in[18];
    float* out = (float*)d_out;

    int N = in_sizes[0] / 6;
    int E = in_sizes[1] / 2;
    int G = out_size;
    const int T = 256;
    int nb = (N + SCAN_BS - 1) / SCAN_BS;
    long long cw = (long long)N * 64 > E ? (long long)N * 64 : E;
    long long fb = E > N ? E : N;

    // build dst-CSR + dinv (xw1 and bounds ride along)
    k_zero_cnt<<<(N + T - 1) / T, T>>>(N);
    k_count_xw1<<<(int)((cw + T - 1) / T), T>>>(ei, x, W1, E, N);
    k_scan1<<<nb, SCAN_BS>>>(N);
    k_scan3<<<nb, SCAN_BS>>>(N, E);
    k_fill_bounds<<<(int)((fb + T - 1) / T), T>>>(ei, batch, E, N, G);

    // layer 1
    k_gather<<<(N * 8 + T - 1) / T, T>>>(N);

    // layer 2
    k_xw2<<<((N + 3) / 4 * 32 + T - 1) / T, T>>>(b1, W2, N);
    k_gather<<<(N * 8 + T - 1) / T, T>>>(N);

    // readout
    k_final<<<(G + 7) / 8, 256>>>(b2, lig, addv, bas, ary, e_l, e_a, e_b, e_r,
                                  l1W, l1b, l2W, l2b, out, G);
}